// round 12
// baseline (speedup 1.0000x reference)
#include <cuda_runtime.h>
#include <cuda_fp16.h>
#include <stdint.h>

#define NIMG 8
#define HH 256
#define WW 256
#define NPIX (NIMG*HH*WW)
#define OT 30                // output tile 30x30; computed patch 32x32
#define NT 9                 // ceil(256/30)
#define NSEG 16              // seed-list segments per image (16 rows each)
#define SEGCAP 32            // capacity per segment (Poisson mean 8.2 -> safe)

// Sentinel-filled seed table: unused slots hold (1e9,1e9), so consumers need
// no counts (sentinels lose every min and fail every prune test).
__device__ float2 g_seed[NIMG][NSEG][SEGCAP];

// ---------------------------------------------------------------------------
// Kernel 1: seed extraction, 128 blocks x 512 threads. Image loads are issued
// FIRST (independent of the sentinel fill) so the DRAM round-trip overlaps the
// fill+sync. ~8 shared atomics per block.
// ---------------------------------------------------------------------------
__global__ __launch_bounds__(512) void extract_kernel(const float* __restrict__ img) {
    __shared__ int scnt;
    const int blk = blockIdx.x;
    const int im  = blk >> 4;
    const int seg = blk & 15;
    const int tid = threadIdx.x;

    const float4* im4 = (const float4*)img;
    const int base4 = (im * 65536 + seg * 4096) >> 2;
    const int p4a = base4 + tid;
    const int p4b = base4 + 512 + tid;
    float4 va = im4[p4a];                 // loads in flight during fill+sync
    float4 vb = im4[p4b];

    if (tid == 0) scnt = 0;
    if (tid < SEGCAP) g_seed[im][seg][tid] = make_float2(1e9f, 1e9f);
    __syncthreads();

#pragma unroll
    for (int h = 0; h < 2; h++) {
        float4 v = h ? vb : va;
        int p4  = h ? p4b : p4a;
        if (v.x != 0.0f || v.y != 0.0f || v.z != 0.0f || v.w != 0.0f) {
            int px0 = p4 << 2;
#pragma unroll
            for (int j = 0; j < 4; j++) {
                float f = (j == 0) ? v.x : (j == 1) ? v.y : (j == 2) ? v.z : v.w;
                if (f != 0.0f) {
                    int px  = px0 + j;
                    int idx = atomicAdd(&scnt, 1);
                    if (idx < SEGCAP)
                        g_seed[im][seg][idx] =
                            make_float2((float)(px & 255), (float)((px >> 8) & 255));
                }
            }
        }
    }
}

// ---------------------------------------------------------------------------
// Kernel 2 (PDL secondary): per-tile prune + fp16x2 chessboard distance +
// softmin-log. Launched with programmatic stream serialization: it starts
// while extract is still running, does its index math, then blocks at
// cudaGridDependencySynchronize() before touching g_seed.
// ---------------------------------------------------------------------------
__global__ __launch_bounds__(256) void main_kernel(float* __restrict__ out) {
    __shared__ uint2          sp[256];       // {(sx,sx),(sy,sy)} as half2 bits
    __shared__ int            scnt;
    __shared__ int            swmin[8];
    __shared__ unsigned short sd[32][34];

    const int img = blockIdx.z;
    const int tx0 = blockIdx.x * OT - 1;
    const int ty0 = blockIdx.y * OT - 1;
    const int tid = threadIdx.x;

    const float fcx = (float)min(max(tx0 + 16, 0), WW - 1);
    const float fcy = (float)min(max(ty0 + 16, 0), HH - 1);

    // Per-pixel constants for the distance phase (independent of seeds)
    const int r  = tid >> 3;
    const int cb = (tid & 7) << 2;
    const int py = min(max(ty0 + r, 0), HH - 1);
    const __half2 fy2 = __float2half2_rn((float)py);
    int x0 = min(max(tx0 + cb + 0, 0), WW - 1);
    int x1 = min(max(tx0 + cb + 1, 0), WW - 1);
    int x2 = min(max(tx0 + cb + 2, 0), WW - 1);
    int x3 = min(max(tx0 + cb + 3, 0), WW - 1);
    const __half2 xa = __halves2half2(__float2half_rn((float)x0),
                                      __float2half_rn((float)x1));
    const __half2 xb = __halves2half2(__float2half_rn((float)x2),
                                      __float2half_rn((float)x3));

    // Wait for extract_kernel's writes to g_seed to be visible
    cudaGridDependencySynchronize();

    const float2* flat = &g_seed[img][0][0];

    // ---- prologue: 2 slots/thread, chebyshev distance to center ----
    float2 ms[2];
    float  mcd[2];
    float mymin = 1e8f;
#pragma unroll
    for (int q = 0; q < 2; q++) {
        float2 sv = flat[tid + q * 256];
        float cd = fmaxf(fabsf(sv.x - fcx), fabsf(sv.y - fcy));
        ms[q] = sv; mcd[q] = cd;
        mymin = fminf(mymin, cd);
    }
    int imin = (int)mymin;                       // sentinel -> 1e8 clamp
    imin = __reduce_min_sync(0xffffffffu, imin);
    if (tid == 0) scnt = 0;
    if ((tid & 31) == 0) swmin[tid >> 5] = imin;
    __syncthreads();
    int dmin = swmin[0];
#pragma unroll
    for (int i = 1; i < 8; i++) dmin = min(dmin, swmin[i]);
    const float thr = (float)(dmin + 32);        // exact dominance bound

    // ---- compact pruned seeds as pre-broadcast half2 pairs ----
#pragma unroll
    for (int q = 0; q < 2; q++) {
        if (mcd[q] <= thr) {                     // sentinels always fail
            int idx = atomicAdd(&scnt, 1);
            if (idx < 256) {
                unsigned hx = (unsigned)__half_as_ushort(__float2half_rn(ms[q].x));
                unsigned hy = (unsigned)__half_as_ushort(__float2half_rn(ms[q].y));
                sp[idx] = make_uint2(hx * 0x00010001u, hy * 0x00010001u);
            }
        }
    }
    __syncthreads();
    const int m = min(scnt, 256);

    // ---- fp16x2 distance over clamped 32x32 patch: 4 x per thread ----
    __half2 aa = __float2half2_rn(300.0f);       // 300 = unreachable marker
    __half2 ab = aa;
#pragma unroll 4
    for (int k = 0; k < m; k++) {
        uint2 pk = sp[k];
        __half2 sx2 = *reinterpret_cast<__half2*>(&pk.x);
        __half2 sy2 = *reinterpret_cast<__half2*>(&pk.y);
        __half2 dy  = __habs2(__hsub2(fy2, sy2));
        __half2 ta  = __hmax2(__habs2(__hsub2(xa, sx2)), dy);
        __half2 tb  = __hmax2(__habs2(__hsub2(xb, sx2)), dy);
        aa = __hmin2(aa, ta);
        ab = __hmin2(ab, tb);
    }
    sd[r][cb + 0] = __half_as_ushort(__low2half(aa));
    sd[r][cb + 1] = __half_as_ushort(__high2half(aa));
    sd[r][cb + 2] = __half_as_ushort(__low2half(ab));
    sd[r][cb + 3] = __half_as_ushort(__high2half(ab));
    __syncthreads();

    // ---- epilogue: integer tap counts, division-free, coalesced ----
    const float w1 = expf(-1.0f / 0.35f);           // edge tap weight
    const float w2 = expf(-sqrtf(2.0f) / 0.35f);    // diagonal tap weight
    const int lane = tid & 31;
    const int rb   = tid >> 5;
    const int gx   = blockIdx.x * OT + lane;
#pragma unroll
    for (int j = 0; j < 4; j++) {
        int iy = rb + j * 8;
        int gy = blockIdx.y * OT + iy;
        if (iy < OT && lane < OT && gy < HH && gx < WW) {
            float fc = __half2float(__ushort_as_half(sd[iy + 1][lane + 1]));
            float res = 0.0f;
            if (fc > 0.5f && fc < 299.0f) {
                unsigned short tb = __half_as_ushort(__float2half_rn(fc - 1.0f));
                int nd = 0, ne = 0;
                nd += (sd[iy    ][lane    ] == tb);
                ne += (sd[iy    ][lane + 1] == tb);
                nd += (sd[iy    ][lane + 2] == tb);
                ne += (sd[iy + 1][lane    ] == tb);
                ne += (sd[iy + 1][lane + 2] == tb);
                nd += (sd[iy + 2][lane    ] == tb);
                ne += (sd[iy + 2][lane + 1] == tb);
                nd += (sd[iy + 2][lane + 2] == tb);
                float s = (float)ne * w1 + (float)nd * w2;
                res = (fc - 1.0f) - 0.35f * __logf(s);
            }
            out[img * HH * WW + gy * WW + gx] = res;
        }
    }
}

extern "C" void kernel_launch(void* const* d_in, const int* in_sizes, int n_in,
                              void* d_out, int out_size) {
    const float* img = (const float*)d_in[0];
    float* out = (float*)d_out;

    extract_kernel<<<NIMG * NSEG, 512>>>(img);

    // Programmatic dependent launch: main starts while extract drains; the
    // device-side cudaGridDependencySynchronize() provides the ordering.
    cudaLaunchConfig_t cfg = {};
    cfg.gridDim  = dim3(NT, NT, NIMG);
    cfg.blockDim = dim3(256, 1, 1);
    cudaLaunchAttribute attr[1];
    attr[0].id = cudaLaunchAttributeProgrammaticStreamSerialization;
    attr[0].val.programmaticStreamSerializationAllowed = 1;
    cfg.attrs = attr;
    cfg.numAttrs = 1;
    cudaLaunchKernelEx(&cfg, main_kernel, out);
}